// round 17
// baseline (speedup 1.0000x reference)
#include <cuda_runtime.h>
#include <cuda_fp16.h>
#include <cstdint>
#include <cstddef>

// Problem constants
#define SQ   1024
#define BB   8
#define EE   1024
#define HH   16
#define DD   64
#define DFF  4096
#define MTOK (SQ * BB)     // 8192
#define E3   (3 * EE)      // 3072

// ---------------------------------------------------------------------------
// Scratch (__device__ globals; no allocations allowed)
// ---------------------------------------------------------------------------
__device__ float g_x[(size_t)MTOK * EE];

// fp16 single-plane activations
__device__ __half g_qkv16[(size_t)MTOK * E3];
__device__ __half g_src16[(size_t)MTOK * EE];
__device__ __half g_ctx16[(size_t)MTOK * EE];
__device__ __half g_x16  [(size_t)MTOK * EE];
__device__ __half g_ff116[(size_t)MTOK * DFF];
__device__ __half g_tmp16[(size_t)MTOK * EE];

// fp16 weights (single plane)
__device__ __half g_inw16[(size_t)E3 * EE];
__device__ __half g_outw16[(size_t)EE * EE];
__device__ __half g_w116[(size_t)DFF * EE];
__device__ __half g_w216[(size_t)EE * DFF];

// ---------------------------------------------------------------------------
// helpers
// ---------------------------------------------------------------------------
__device__ __forceinline__ uint32_t smem_u32(const void* p) {
    uint32_t a;
    asm("{ .reg .u64 t; cvta.to.shared.u64 t, %1; cvt.u32.u64 %0, t; }"
        : "=r"(a) : "l"(p));
    return a;
}
__device__ __forceinline__ void cpasync16(uint32_t s, const void* g) {
    asm volatile("cp.async.cg.shared.global [%0], [%1], 16;" :: "r"(s), "l"(g));
}
__device__ __forceinline__ void ldsm4(uint32_t r[4], uint32_t addr) {
    asm volatile("ldmatrix.sync.aligned.m8n8.x4.shared.b16 {%0,%1,%2,%3}, [%4];"
                 : "=r"(r[0]), "=r"(r[1]), "=r"(r[2]), "=r"(r[3]) : "r"(addr));
}
__device__ __forceinline__ void ldsm4t(uint32_t r[4], uint32_t addr) {
    asm volatile("ldmatrix.sync.aligned.m8n8.x4.trans.shared.b16 {%0,%1,%2,%3}, [%4];"
                 : "=r"(r[0]), "=r"(r[1]), "=r"(r[2]), "=r"(r[3]) : "r"(addr));
}
__device__ __forceinline__ void mma16816(float c[4], const uint32_t a[4],
                                         uint32_t b0, uint32_t b1) {
    asm volatile(
        "mma.sync.aligned.m16n8k16.row.col.f32.f16.f16.f32 "
        "{%0,%1,%2,%3}, {%4,%5,%6,%7}, {%8,%9}, {%0,%1,%2,%3};"
        : "+f"(c[0]), "+f"(c[1]), "+f"(c[2]), "+f"(c[3])
        : "r"(a[0]), "r"(a[1]), "r"(a[2]), "r"(a[3]), "r"(b0), "r"(b1));
}
__device__ __forceinline__ uint32_t packh2(float x, float y) {
    __half2 h = __floats2half2_rn(x, y);
    return *reinterpret_cast<uint32_t*>(&h);
}
__device__ __forceinline__ float ex2(float x) {
    float r;
    asm("ex2.approx.f32 %0, %1;" : "=f"(r) : "f"(x));
    return r;
}

// ---------------------------------------------------------------------------
// fused fp32 -> fp16 convert for all 5 tensors (one launch)
// ---------------------------------------------------------------------------
#define N4_INW  ((E3 * EE) / 4)            // 786432
#define N4_OUTW ((EE * EE) / 4)            // 262144
#define N4_W1   ((DFF * EE) / 4)           // 1048576
#define N4_W2   ((EE * DFF) / 4)           // 1048576
#define N4_SRC  ((MTOK * EE) / 4)          // 2097152
#define N4_TOTAL (N4_INW + N4_OUTW + N4_W1 + N4_W2 + N4_SRC)

__global__ __launch_bounds__(256)
void cvt5_kernel(const float* __restrict__ inw,  __half* __restrict__ oinw,
                 const float* __restrict__ outw, __half* __restrict__ ooutw,
                 const float* __restrict__ w1,   __half* __restrict__ ow1,
                 const float* __restrict__ w2,   __half* __restrict__ ow2,
                 const float* __restrict__ src,  __half* __restrict__ osrc)
{
    int i = blockIdx.x * blockDim.x + threadIdx.x;
    if (i >= N4_TOTAL) return;
    const float* in; __half* o;
    if (i < N4_INW)                          { in = inw;  o = oinw; }
    else if ((i -= N4_INW)  < N4_OUTW)       { in = outw; o = ooutw; }
    else if ((i -= N4_OUTW) < N4_W1)         { in = w1;   o = ow1; }
    else if ((i -= N4_W1)   < N4_W2)         { in = w2;   o = ow2; }
    else { i -= N4_W2;                         in = src;  o = osrc; }
    float4 v = ((const float4*)in)[i];
    uint2 p;
    p.x = packh2(v.x, v.y);
    p.y = packh2(v.z, v.w);
    ((uint2*)o)[i] = p;
}

// ---------------------------------------------------------------------------
// Tensor-core GEMM, fp16 single-pass: C = A[M,K] @ B[N,K]^T + bias
// CTA 128x256, BK=64, 256 threads (8 warps as 2x4, warp tile 64x64).
// MMA:LDSM = 32:8 per k16 step. Single-sync 2-stage cp.async pipeline.
// EPI: 1 = bias+relu -> fp16 C16;  2 = bias -> fp16 C16
// ---------------------------------------------------------------------------
#define TSTRIDE 144
#define APLANE  (128 * TSTRIDE)          // 18432 B
#define BPLANE  (256 * TSTRIDE)          // 36864 B
#define STAGE   (APLANE + BPLANE)        // 55296 B
#define GSMEM   (2 * STAGE)              // 110592 B

template <int EPI>
__global__ __launch_bounds__(256, 1)
void gemm_mma(const __half* __restrict__ Ag, const __half* __restrict__ Bg,
              const float* __restrict__ bias,
              __half* __restrict__ C16,
              int Ndim, int Kdim)
{
    extern __shared__ char sm[];
    const int t    = threadIdx.x;
    const int lane = t & 31;
    const int wid  = t >> 5;
    const int wm   = (wid & 1) * 64;      // 2 M-warps
    const int wn   = (wid >> 1) * 64;     // 4 N-warps
    const int bm   = blockIdx.y * 128;
    const int bn   = blockIdx.x * 256;

    const uint32_t smb = smem_u32(sm);

    auto issue = [&](int k0, int buf) {
        uint32_t sb = smb + buf * STAGE;
#pragma unroll
        for (int i = 0; i < 4; i++) {                 // A: 128 rows x 8 chunks
            int e = t + i * 256;
            int r = e >> 3, c = e & 7;
            cpasync16(sb + (uint32_t)(r * TSTRIDE + c * 16),
                      Ag + (size_t)(bm + r) * Kdim + k0 + c * 8);
        }
#pragma unroll
        for (int i = 0; i < 8; i++) {                 // B: 256 rows x 8 chunks
            int e = t + i * 256;
            int r = e >> 3, c = e & 7;
            cpasync16(sb + APLANE + (uint32_t)(r * TSTRIDE + c * 16),
                      Bg + (size_t)(bn + r) * Kdim + k0 + c * 8);
        }
        asm volatile("cp.async.commit_group;");
    };

    float acc[4][8][4];
#pragma unroll
    for (int i = 0; i < 4; i++)
#pragma unroll
        for (int j = 0; j < 8; j++)
#pragma unroll
            for (int k = 0; k < 4; k++) acc[i][j][k] = 0.0f;

    const int kc = Kdim / 64;
    issue(0, 0);

    for (int ic = 0; ic < kc; ic++) {
        const int buf = ic & 1;
        asm volatile("cp.async.wait_group 0;");
        __syncthreads();
        if (ic + 1 < kc) issue((ic + 1) * 64, buf ^ 1);

        const uint32_t pA = smb + buf * STAGE;
        const uint32_t pB = pA + APLANE;

#pragma unroll
        for (int ks = 0; ks < 4; ks++) {
            uint32_t Af[4][4];
#pragma unroll
            for (int i = 0; i < 4; i++) {
                uint32_t off = (uint32_t)((wm + i * 16 + (lane & 15)) * TSTRIDE
                               + ks * 32 + ((lane >> 4) << 4));
                ldsm4(Af[i], pA + off);
            }
            uint32_t Bf[4][4];
#pragma unroll
            for (int g = 0; g < 4; g++) {
                int nb = wn + g * 16;
                uint32_t off = (uint32_t)((nb + (lane & 7) + ((lane >> 4) << 3)) * TSTRIDE
                               + ks * 32 + (((lane >> 3) & 1) << 4));
                ldsm4(Bf[g], pB + off);
            }
#pragma unroll
            for (int g = 0; g < 4; g++)
#pragma unroll
                for (int jj = 0; jj < 2; jj++) {
                    int j = g * 2 + jj;
                    uint32_t b0 = Bf[g][jj * 2], b1 = Bf[g][jj * 2 + 1];
#pragma unroll
                    for (int i = 0; i < 4; i++)
                        mma16816(acc[i][j], Af[i], b0, b1);
                }
        }
    }

#pragma unroll
    for (int i = 0; i < 4; i++) {
        const int r0 = bm + wm + i * 16 + (lane >> 2);
#pragma unroll
        for (int j = 0; j < 8; j++) {
            const int c = bn + wn + j * 8 + 2 * (lane & 3);
            const float bx = bias[c], by = bias[c + 1];
            float v0x = acc[i][j][0] + bx, v0y = acc[i][j][1] + by;
            float v1x = acc[i][j][2] + bx, v1y = acc[i][j][3] + by;
            if (EPI == 1) {
                v0x = fmaxf(v0x, 0.f); v0y = fmaxf(v0y, 0.f);
                v1x = fmaxf(v1x, 0.f); v1y = fmaxf(v1y, 0.f);
            }
            *(uint32_t*)(C16 + (size_t)r0 * Ndim + c)       = packh2(v0x, v0y);
            *(uint32_t*)(C16 + (size_t)(r0 + 8) * Ndim + c) = packh2(v1x, v1y);
        }
    }
}

// ---------------------------------------------------------------------------
// Flash attention via mma.sync fp16 (unchanged from round 16)
// ---------------------------------------------------------------------------
#define ATS 144
#define ATILE (64 * ATS)
#define SCALE_LOG2E 0.18033688011112042f   // 0.125 * log2(e)

__global__ __launch_bounds__(128)
void attn_mma(const __half* __restrict__ qkv, __half* __restrict__ ctx)
{
    __shared__ __align__(16) char smQ[ATILE];
    __shared__ __align__(16) char smK[2][ATILE];
    __shared__ __align__(16) char smV[2][ATILE];

    const int qt = blockIdx.x & 15;
    const int bh = blockIdx.x >> 4;
    const int b  = bh / HH;
    const int h  = bh % HH;
    const int t  = threadIdx.x;
    const int lane = t & 31;
    const int w  = t >> 5;
    const int q0 = w * 16;

    const size_t rowstride = (size_t)BB * E3;
    const __half* Qg = qkv + ((size_t)(qt * 64) * BB + b) * E3 + h * DD;
    const __half* Kg = qkv + (size_t)b * E3 + EE + h * DD;
    const __half* Vg = Kg + EE;

    const uint32_t uQ = smem_u32(smQ);
    const uint32_t uK = smem_u32(smK[0]);
    const uint32_t uV = smem_u32(smV[0]);

    auto issue_kv = [&](int kt, int buf) {
#pragma unroll
        for (int i = 0; i < 4; i++) {
            int e = t + i * 128;
            int r = e >> 3, c = e & 7;
            uint32_t off = (uint32_t)(r * ATS + c * 16) + (uint32_t)(buf * ATILE);
            size_t g = (size_t)(kt * 64 + r) * rowstride + c * 8;
            cpasync16(uK + off, Kg + g);
            cpasync16(uV + off, Vg + g);
        }
        asm volatile("cp.async.commit_group;");
    };

#pragma unroll
    for (int i = 0; i < 4; i++) {
        int e = t + i * 128;
        int r = e >> 3, c = e & 7;
        uint32_t off = (uint32_t)(r * ATS + c * 16);
        size_t g = (size_t)r * rowstride + c * 8;
        cpasync16(uQ + off, Qg + g);
        cpasync16(uK + off, Kg + g);
        cpasync16(uV + off, Vg + g);
    }
    asm volatile("cp.async.commit_group;");

    uint32_t Aq[4][4];
    float oacc[8][4];
#pragma unroll
    for (int j = 0; j < 8; j++)
#pragma unroll
        for (int e = 0; e < 4; e++) oacc[j][e] = 0.0f;
    float m0 = -1e30f, m1 = -1e30f, l0 = 0.0f, l1 = 0.0f;

    for (int kt = 0; kt < 16; kt++) {
        const int buf = kt & 1;
        asm volatile("cp.async.wait_group 0;");
        __syncthreads();
        if (kt + 1 < 16) issue_kv(kt + 1, buf ^ 1);

        if (kt == 0) {
#pragma unroll
            for (int ks = 0; ks < 4; ks++) {
                uint32_t off = (uint32_t)((q0 + (lane & 15)) * ATS + ks * 32 + ((lane >> 4) << 4));
                ldsm4(Aq[ks], uQ + off);
            }
        }
        const uint32_t pK = uK + buf * ATILE;
        const uint32_t pV = uV + buf * ATILE;

        float sacc[8][4];
#pragma unroll
        for (int j = 0; j < 8; j++)
#pragma unroll
            for (int e = 0; e < 4; e++) sacc[j][e] = 0.0f;
#pragma unroll
        for (int ks = 0; ks < 4; ks++) {
#pragma unroll
            for (int g = 0; g < 4; g++) {
                uint32_t Kf[4];
                uint32_t off = (uint32_t)((g * 16 + (lane & 7) + ((lane >> 4) << 3)) * ATS
                               + ks * 32 + (((lane >> 3) & 1) << 4));
                ldsm4(Kf, pK + off);
                mma16816(sacc[g * 2],     Aq[ks], Kf[0], Kf[1]);
                mma16816(sacc[g * 2 + 1], Aq[ks], Kf[2], Kf[3]);
            }
        }

        float mx0 = -1e30f, mx1 = -1e30f;
#pragma unroll
        for (int j = 0; j < 8; j++) {
            sacc[j][0] *= SCALE_LOG2E; sacc[j][1] *= SCALE_LOG2E;
            sacc[j][2] *= SCALE_LOG2E; sacc[j][3] *= SCALE_LOG2E;
            mx0 = fmaxf(mx0, fmaxf(sacc[j][0], sacc[j][1]));
            mx1 = fmaxf(mx1, fmaxf(sacc[j][2], sacc[j][3]));
        }
        mx0 = fmaxf(mx0, __shfl_xor_sync(0xffffffffu, mx0, 1));
        mx0 = fmaxf(mx0, __shfl_xor_sync(0xffffffffu, mx0, 2));
        mx1 = fmaxf(mx1, __shfl_xor_sync(0xffffffffu, mx1, 1));
        mx1 = fmaxf(mx1, __shfl_xor_sync(0xffffffffu, mx1, 2));

        float nm0 = fmaxf(m0, mx0), nm1 = fmaxf(m1, mx1);
        float c0 = ex2(m0 - nm0), c1 = ex2(m1 - nm1);

        float s0 = 0.0f, s1 = 0.0f;
        uint32_t Pa[4][4];
#pragma unroll
        for (int j = 0; j < 8; j++) {
            float p0 = ex2(sacc[j][0] - nm0);
            float p1 = ex2(sacc[j][1] - nm0);
            float p2 = ex2(sacc[j][2] - nm1);
            float p3 = ex2(sacc[j][3] - nm1);
            s0 += p0 + p1; s1 += p2 + p3;
            const int ks = j >> 1, hi = j & 1;
            Pa[ks][hi * 2]     = packh2(p0, p1);
            Pa[ks][hi * 2 + 1] = packh2(p2, p3);
        }
        s0 += __shfl_xor_sync(0xffffffffu, s0, 1);
        s0 += __shfl_xor_sync(0xffffffffu, s0, 2);
        s1 += __shfl_xor_sync(0xffffffffu, s1, 1);
        s1 += __shfl_xor_sync(0xffffffffu, s1, 2);

        l0 = l0 * c0 + s0;  l1 = l1 * c1 + s1;
        m0 = nm0;           m1 = nm1;
#pragma unroll
        for (int j = 0; j < 8; j++) {
            oacc[j][0] *= c0; oacc[j][1] *= c0;
            oacc[j][2] *= c1; oacc[j][3] *= c1;
        }

#pragma unroll
        for (int ks = 0; ks < 4; ks++) {
#pragma unroll
            for (int dg = 0; dg < 4; dg++) {
                uint32_t Vf[4];
                uint32_t off = (uint32_t)((ks * 16 + (lane & 7) + (((lane >> 3) & 1) << 3)) * ATS
                               + dg * 32 + ((lane >> 4) << 4));
                ldsm4t(Vf, pV + off);
                mma16816(oacc[dg * 2],     Pa[ks], Vf[0], Vf[1]);
                mma16816(oacc[dg * 2 + 1], Pa[ks], Vf[2], Vf[3]);
            }
        }
    }

    const float i0 = 1.0f / l0, i1 = 1.0f / l1;
    const int r0 = qt * 64 + q0 + (lane >> 2);
#pragma unroll
    for (int j = 0; j < 8; j++) {
        const int col = h * DD + j * 8 + 2 * (lane & 3);
        *(uint32_t*)(ctx + ((size_t)r0 * BB + b) * EE + col) =
            packh2(oacc[j][0] * i0, oacc[j][1] * i0);
        *(uint32_t*)(ctx + ((size_t)(r0 + 8) * BB + b) * EE + col) =
            packh2(oacc[j][2] * i1, oacc[j][3] * i1);
    }
}

// ---------------------------------------------------------------------------
// out = layernorm(a + bres16) * g + beta; residual read as fp16.
// CVT=1 also writes fp16 plane.
// ---------------------------------------------------------------------------
template <int CVT>
__global__ __launch_bounds__(256)
void add_ln_kernel(const float* __restrict__ a, const __half* __restrict__ bres16,
                   const float* __restrict__ g, const float* __restrict__ beta,
                   float* __restrict__ out, __half* __restrict__ o16)
{
    const int row = blockIdx.x;
    const int t   = threadIdx.x;
    const float4* A4 = (const float4*)(a + (size_t)row * EE);

    float4 x = A4[t];
    uint2 bp = ((const uint2*)(bres16 + (size_t)row * EE))[t];
    __half2 b0 = *reinterpret_cast<__half2*>(&bp.x);
    __half2 b1 = *reinterpret_cast<__half2*>(&bp.y);
    x.x += __half2float(b0.x); x.y += __half2float(b0.y);
    x.z += __half2float(b1.x); x.w += __half2float(b1.y);

    float s  = x.x + x.y + x.z + x.w;
    float ss = x.x * x.x + x.y * x.y + x.z * x.z + x.w * x.w;

#pragma unroll
    for (int off = 16; off > 0; off >>= 1) {
        s  += __shfl_xor_sync(0xffffffffu, s,  off);
        ss += __shfl_xor_sync(0xffffffffu, ss, off);
    }
    __shared__ float sh_s[8], sh_ss[8];
    const int w = t >> 5, l = t & 31;
    if (l == 0) { sh_s[w] = s; sh_ss[w] = ss; }
    __syncthreads();
    s = 0.0f; ss = 0.0f;
#pragma unroll
    for (int i = 0; i < 8; i++) { s += sh_s[i]; ss += sh_ss[i]; }

    const float mean = s * (1.0f / EE);
    const float var  = ss * (1.0f / EE) - mean * mean;
    const float rstd = rsqrtf(var + 1e-5f);

    float4 g4 = ((const float4*)g)[t];
    float4 b4 = ((const float4*)beta)[t];
    float4 o;
    o.x = (x.x - mean) * rstd * g4.x + b4.x;
    o.y = (x.y - mean) * rstd * g4.y + b4.y;
    o.z = (x.z - mean) * rstd * g4.z + b4.z;
    o.w = (x.w - mean) * rstd * g4.w + b4.w;
    ((float4*)(out + (size_t)row * EE))[t] = o;

    if (CVT) {
        uint2 p;
        p.x = packh2(o.x, o.y);
        p.y = packh2(o.z, o.w);
        ((uint2*)(o16 + (size_t)row * EE))[t] = p;
    }
}

// ---------------------------------------------------------------------------
// launch
// ---------------------------------------------------------------------------
extern "C" void kernel_launch(void* const* d_in, const int* in_sizes, int n_in,
                              void* d_out, int out_size)
{
    const float* src    = (const float*)d_in[0];
    const float* in_w   = (const float*)d_in[1];
    const float* in_b   = (const float*)d_in[2];
    const float* out_w  = (const float*)d_in[3];
    const float* out_b  = (const float*)d_in[4];
    const float* ln1g   = (const float*)d_in[5];
    const float* ln1b   = (const float*)d_in[6];
    const float* ln2g   = (const float*)d_in[7];
    const float* ln2b   = (const float*)d_in[8];
    const float* w1     = (const float*)d_in[9];
    const float* b1     = (const float*)d_in[10];
    const float* w2     = (const float*)d_in[11];
    const float* b2     = (const float*)d_in[12];
    float* out = (float*)d_out;

    float* x;
    cudaGetSymbolAddress((void**)&x, g_x);

    __half *qkv16, *src16, *ctx16, *x16, *ff116, *tmp16;
    __half *inw16, *outw16, *w116, *w216;
    cudaGetSymbolAddress((void**)&qkv16, g_qkv16);
    cudaGetSymbolAddress((void**)&src16, g_src16);
    cudaGetSymbolAddress((void**)&ctx16, g_ctx16);
    cudaGetSymbolAddress((void**)&x16,   g_x16);
    cudaGetSymbolAddress((void**)&ff116, g_ff116);
    cudaGetSymbolAddress((void**)&tmp16, g_tmp16);
    cudaGetSymbolAddress((void**)&inw16,  g_inw16);
    cudaGetSymbolAddress((void**)&outw16, g_outw16);
    cudaGetSymbolAddress((void**)&w116,   g_w116);
    cudaGetSymbolAddress((void**)&w216,   g_w216);

    cudaFuncSetAttribute(gemm_mma<1>, cudaFuncAttributeMaxDynamicSharedMemorySize, GSMEM);
    cudaFuncSetAttribute(gemm_mma<2>, cudaFuncAttributeMaxDynamicSharedMemorySize, GSMEM);

    // 0. one-time fp16 converts (weights + src), single launch
    cvt5_kernel<<<(N4_TOTAL + 255) / 256, 256>>>(
        in_w, inw16, out_w, outw16, w1, w116, w2, w216, src, src16);

    // 1. qkv = src @ in_proj_w^T + b        (8192 x 3072 x 1024) -> fp16
    gemm_mma<2><<<dim3(E3 / 256, MTOK / 128), 256, GSMEM>>>(
        src16, inw16, in_b, qkv16, E3, EE);
    // 2. flash attention (mma.sync fp16) -> ctx fp16
    attn_mma<<<BB * HH * 16, 128>>>(qkv16, ctx16);
    // 3. attn_out = ctx @ out_w^T + out_b   (8192 x 1024 x 1024) -> fp16 tmp16
    gemm_mma<2><<<dim3(EE / 256, MTOK / 128), 256, GSMEM>>>(
        ctx16, outw16, out_b, tmp16, EE, EE);
    // 4. x = LN1(src + tmp16) -> fp32 x + fp16 x16
    add_ln_kernel<1><<<MTOK, 256>>>(src, tmp16, ln1g, ln1b, x, x16);
    // 5. ff1 = relu(x @ w1^T + b1)          (8192 x 4096 x 1024) -> fp16
    gemm_mma<1><<<dim3(DFF / 256, MTOK / 128), 256, GSMEM>>>(
        x16, w116, b1, ff116, DFF, EE);
    // 6. ff2 = ff1 @ w2^T + b2              (8192 x 1024 x 4096) -> fp16 tmp16
    gemm_mma<2><<<dim3(EE / 256, MTOK / 128), 256, GSMEM>>>(
        ff116, w216, b2, tmp16, EE, DFF);
    // 7. out = LN2(x + tmp16)
    add_ln_kernel<0><<<MTOK, 256>>>(x, tmp16, ln2g, ln2b, out, nullptr);
}